// round 15
// baseline (speedup 1.0000x reference)
#include <cuda_runtime.h>
#include <cuda_bf16.h>
#include <cstdint>

// Problem constants
#define BATCH    2
#define SEQ      2048
#define HID      4096
#define NHEADS   32
#define NKV      8
#define HDIM     128
#define QKV_N    6144          // 32*128 + 8*128 + 8*128
#define MTOK     (BATCH*SEQ)   // 4096 token rows

// ---------------------------------------------------------------------------
// Scratch (device globals: allowed; no runtime allocation)
// ---------------------------------------------------------------------------
__device__ float g_qkv[(size_t)MTOK * QKV_N];    // fp32 qkv after projection

__device__ __nv_bfloat16 g_hid_hi[(size_t)MTOK * HID];
__device__ __nv_bfloat16 g_hid_lo[(size_t)MTOK * HID];
__device__ __nv_bfloat16 g_wqkv_hi[(size_t)QKV_N * HID];
__device__ __nv_bfloat16 g_wqkv_lo[(size_t)QKV_N * HID];
__device__ __nv_bfloat16 g_attn_hi[(size_t)MTOK * HID];
__device__ __nv_bfloat16 g_attn_lo[(size_t)MTOK * HID];
__device__ __nv_bfloat16 g_wo_hi[(size_t)HID * HID];
__device__ __nv_bfloat16 g_wo_lo[(size_t)HID * HID];

// rope'd q/k and v, split bf16 hi/lo
__device__ __nv_bfloat16 g_q_hi[(size_t)MTOK * NHEADS * HDIM];
__device__ __nv_bfloat16 g_q_lo[(size_t)MTOK * NHEADS * HDIM];
__device__ __nv_bfloat16 g_k_hi[(size_t)MTOK * NKV * HDIM];
__device__ __nv_bfloat16 g_k_lo[(size_t)MTOK * NKV * HDIM];
__device__ __nv_bfloat16 g_v_hi[(size_t)MTOK * NKV * HDIM];
__device__ __nv_bfloat16 g_v_lo[(size_t)MTOK * NKV * HDIM];

// ---------------------------------------------------------------------------
// mma.sync + ldmatrix + cp.async helpers (family-agnostic on .target sm_100)
// ---------------------------------------------------------------------------
__device__ __forceinline__ uint32_t smem_u32(const void* p) {
    uint32_t a;
    asm("{ .reg .u64 t; cvta.to.shared.u64 t, %1; cvt.u32.u64 %0, t; }"
        : "=r"(a) : "l"(p));
    return a;
}
__device__ __forceinline__ void ldsm4(uint32_t* r, uint32_t addr) {
    asm volatile("ldmatrix.sync.aligned.m8n8.x4.shared.b16 {%0,%1,%2,%3}, [%4];"
        : "=r"(r[0]), "=r"(r[1]), "=r"(r[2]), "=r"(r[3]) : "r"(addr));
}
__device__ __forceinline__ void ldsm4t(uint32_t* r, uint32_t addr) {
    asm volatile("ldmatrix.sync.aligned.m8n8.x4.trans.shared.b16 {%0,%1,%2,%3}, [%4];"
        : "=r"(r[0]), "=r"(r[1]), "=r"(r[2]), "=r"(r[3]) : "r"(addr));
}
__device__ __forceinline__ void mma_bf16(float* d, const uint32_t* a, const uint32_t* b) {
    asm volatile(
        "mma.sync.aligned.m16n8k16.row.col.f32.bf16.bf16.f32 "
        "{%0,%1,%2,%3}, {%4,%5,%6,%7}, {%8,%9}, {%0,%1,%2,%3};"
        : "+f"(d[0]), "+f"(d[1]), "+f"(d[2]), "+f"(d[3])
        : "r"(a[0]), "r"(a[1]), "r"(a[2]), "r"(a[3]), "r"(b[0]), "r"(b[1]));
}
__device__ __forceinline__ void cp_async16(uint32_t s, const void* g) {
    asm volatile("cp.async.cg.shared.global [%0], [%1], 16;" :: "r"(s), "l"(g));
}
#define CP_COMMIT() asm volatile("cp.async.commit_group;" ::: "memory")

__device__ __forceinline__ uint32_t pack_bf16(float x, float y) {
    __nv_bfloat162 t = __floats2bfloat162_rn(x, y);
    return *(uint32_t*)&t;
}

// ---------------------------------------------------------------------------
// fp32 -> bf16 (hi, lo) splitter
// ---------------------------------------------------------------------------
__global__ __launch_bounds__(256) void split_bf16_kernel(
    const float* __restrict__ x,
    __nv_bfloat16* __restrict__ hi,
    __nv_bfloat16* __restrict__ lo,
    size_t n)
{
    size_t i = ((size_t)blockIdx.x * blockDim.x + threadIdx.x) * 4;
    if (i >= n) return;
    float4 v = *(const float4*)(x + i);
    float vs[4] = {v.x, v.y, v.z, v.w};
    __nv_bfloat16 h[4], l[4];
#pragma unroll
    for (int k = 0; k < 4; k++) {
        h[k] = __float2bfloat16(vs[k]);
        l[k] = __float2bfloat16(vs[k] - __bfloat162float(h[k]));
    }
    *(__nv_bfloat162*)(hi + i)     = __nv_bfloat162(h[0], h[1]);
    *(__nv_bfloat162*)(hi + i + 2) = __nv_bfloat162(h[2], h[3]);
    *(__nv_bfloat162*)(lo + i)     = __nv_bfloat162(l[0], l[1]);
    *(__nv_bfloat162*)(lo + i + 2) = __nv_bfloat162(l[2], l[3]);
}

// ---------------------------------------------------------------------------
// Tensor-core GEMM v4 (TN): CTA tile 64(M)x128(N), K-chunk 64, 128 threads =
// 4 warps (2m x 2n), warp tile 32x64 -> 12 ldsm feed 48 mma per warp-ks
// (128 B/mma smem read vs 170 before). 2-stage cp.async, 96KB -> 2 CTA/SM.
// Stage layout: Ahi[64][64] Alo | Bhi[128][64] Blo (16KB + 32KB = 48KB).
// ---------------------------------------------------------------------------
#define GS_STAGE   49152
#define GEMM_SMEM_BYTES (2 * GS_STAGE)

__device__ __forceinline__ void gemm_stage_load(
    uint32_t stu,
    const __nv_bfloat16* __restrict__ gAhi, const __nv_bfloat16* __restrict__ gAlo,
    const __nv_bfloat16* __restrict__ gBhi, const __nv_bfloat16* __restrict__ gBlo,
    int K, int ko, int tid)
{
#pragma unroll
    for (int i = 0; i < 8; i++) {           // A tiles: 2 x 64 rows x 8 = 1024 units
        int lin = tid + 128 * i;
        int tile = lin >> 9, rem = lin & 511;
        int r = rem >> 3, u = rem & 7;
        const __nv_bfloat16* g = (tile ? gAlo : gAhi) + (size_t)r * K + ko + u * 8;
        cp_async16(stu + tile * 8192 + r * 128 + ((u ^ (r & 7)) << 4), g);
    }
#pragma unroll
    for (int i = 0; i < 16; i++) {          // B tiles: 2 x 128 rows x 8 = 2048 units
        int lin = tid + 128 * i;
        int tile = lin >> 10, rem = lin & 1023;
        int r = rem >> 3, u = rem & 7;
        const __nv_bfloat16* g = (tile ? gBlo : gBhi) + (size_t)r * K + ko + u * 8;
        cp_async16(stu + 16384 + tile * 16384 + r * 128 + ((u ^ (r & 7)) << 4), g);
    }
    CP_COMMIT();
}

__global__ __launch_bounds__(128) void mma_gemm_ca(
    const __nv_bfloat16* __restrict__ Ahi, const __nv_bfloat16* __restrict__ Alo,
    const __nv_bfloat16* __restrict__ Bhi, const __nv_bfloat16* __restrict__ Blo,
    float* __restrict__ C, int M, int N, int K)
{
    extern __shared__ char smem[];
    const uint32_t smem_u = smem_u32(smem);
    const int tid  = threadIdx.x;
    const int wid  = tid >> 5;
    const int lane = tid & 31;
    const int warp_m = wid & 1;             // 2 x 32 rows
    const int warp_n = wid >> 1;            // 2 x 64 cols

    const int bm = blockIdx.y * 64;
    const int bn = blockIdx.x * 128;

    const int grp = lane >> 3, tt = lane & 7;
    const int rowA = tt + (grp & 1) * 8, duA = grp >> 1;
    const int rowB = tt + (grp >> 1) * 8, duB = grp & 1;

    const __nv_bfloat16* gAhi = Ahi + (size_t)bm * K;
    const __nv_bfloat16* gAlo = Alo + (size_t)bm * K;
    const __nv_bfloat16* gBhi = Bhi + (size_t)bn * K;
    const __nv_bfloat16* gBlo = Blo + (size_t)bn * K;

    float acc[2][8][4];
#pragma unroll
    for (int i = 0; i < 2; i++)
#pragma unroll
        for (int j = 0; j < 8; j++)
#pragma unroll
            for (int r = 0; r < 4; r++) acc[i][j][r] = 0.0f;

    const int nch = K >> 6;
    gemm_stage_load(smem_u, gAhi, gAlo, gBhi, gBlo, K, 0, tid);

    for (int kc = 0; kc < nch; kc++) {
        asm volatile("cp.async.wait_group 0;" ::: "memory");
        __syncthreads();

        if (kc + 1 < nch)
            gemm_stage_load(smem_u + ((kc + 1) & 1) * GS_STAGE,
                            gAhi, gAlo, gBhi, gBlo, K, (kc + 1) << 6, tid);

        const uint32_t st  = smem_u + (kc & 1) * GS_STAGE;
        const uint32_t stAh = st,           stAl = st + 8192;
        const uint32_t stBh = st + 16384,   stBl = st + 32768;

#pragma unroll
        for (int ks = 0; ks < 4; ks++) {
            const int u0 = ks * 2;
            uint32_t aH[2][4], aL[2][4];
#pragma unroll
            for (int mt = 0; mt < 2; mt++) {
                int row = warp_m * 32 + mt * 16 + rowA;
                uint32_t off = row * 128 + (((u0 + duA) ^ (row & 7)) << 4);
                ldsm4(aH[mt], stAh + off);
                ldsm4(aL[mt], stAl + off);
            }
#pragma unroll
            for (int p = 0; p < 4; p++) {
                int row = warp_n * 64 + p * 16 + rowB;
                uint32_t off = row * 128 + (((u0 + duB) ^ (row & 7)) << 4);
                uint32_t rh[4], rl[4];
                ldsm4(rh, stBh + off);
                ldsm4(rl, stBl + off);
                uint32_t bh0[2] = {rh[0], rh[1]}, bh1[2] = {rh[2], rh[3]};
                uint32_t bl0[2] = {rl[0], rl[1]}, bl1[2] = {rl[2], rl[3]};
#pragma unroll
                for (int mt = 0; mt < 2; mt++) {
                    mma_bf16(acc[mt][2*p],   aH[mt], bh0);
                    mma_bf16(acc[mt][2*p],   aH[mt], bl0);
                    mma_bf16(acc[mt][2*p],   aL[mt], bh0);
                    mma_bf16(acc[mt][2*p+1], aH[mt], bh1);
                    mma_bf16(acc[mt][2*p+1], aH[mt], bl1);
                    mma_bf16(acc[mt][2*p+1], aL[mt], bh1);
                }
            }
        }
    }

#pragma unroll
    for (int mt = 0; mt < 2; mt++) {
        int row = bm + warp_m * 32 + mt * 16 + (lane >> 2);
#pragma unroll
        for (int nt = 0; nt < 8; nt++) {
            int col = bn + warp_n * 64 + nt * 8 + (lane & 3) * 2;
            *(float2*)(C + (size_t)row * N + col) =
                make_float2(acc[mt][nt][0], acc[mt][nt][1]);
            *(float2*)(C + (size_t)(row + 8) * N + col) =
                make_float2(acc[mt][nt][2], acc[mt][nt][3]);
        }
    }
}

// ---------------------------------------------------------------------------
// RoPE + split: reads fp32 g_qkv, writes bf16 hi/lo q (pre-scaled), k, v.
// ---------------------------------------------------------------------------
__global__ __launch_bounds__(256) void rope_split_kernel(
    const float* __restrict__ qkv, const int* __restrict__ positions,
    __nv_bfloat16* __restrict__ qhi, __nv_bfloat16* __restrict__ qlo,
    __nv_bfloat16* __restrict__ khi, __nv_bfloat16* __restrict__ klo,
    __nv_bfloat16* __restrict__ vhi, __nv_bfloat16* __restrict__ vlo)
{
    int idx  = blockIdx.x * blockDim.x + threadIdx.x;
    int d    = idx & 63;
    int t    = idx >> 6;
    int head = t % 48;
    int tok  = t / 48;
    const float scale = 0.08838834764831845f;   // 1/sqrt(128)

    if (head < 40) {
        float pos = (float)positions[tok];
        float freq = pos * expf(-(float)d * 0.21586735246819178f);
        float s, c;
        sincosf(freq, &s, &c);
        const float* p = qkv + (size_t)tok * QKV_N +
                         (head < 32 ? head * 128 : 4096 + (head - 32) * 128);
        float x1 = p[d], x2 = p[d + 64];
        float r1 = x1 * c - x2 * s;
        float r2 = x2 * c + x1 * s;
        __nv_bfloat16 *dh, *dl;
        if (head < 32) {
            r1 *= scale; r2 *= scale;
            size_t o = ((size_t)tok * NHEADS + head) * HDIM;
            dh = qhi + o; dl = qlo + o;
        } else {
            size_t o = ((size_t)tok * NKV + (head - 32)) * HDIM;
            dh = khi + o; dl = klo + o;
        }
        __nv_bfloat16 h1 = __float2bfloat16(r1);
        __nv_bfloat16 h2 = __float2bfloat16(r2);
        dh[d]      = h1;  dl[d]      = __float2bfloat16(r1 - __bfloat162float(h1));
        dh[d + 64] = h2;  dl[d + 64] = __float2bfloat16(r2 - __bfloat162float(h2));
    } else {
        int gk = head - 40;
        const float* p = qkv + (size_t)tok * QKV_N + 5120 + gk * 128;
        size_t o = ((size_t)tok * NKV + gk) * HDIM;
        float x1 = p[d], x2 = p[d + 64];
        __nv_bfloat16 h1 = __float2bfloat16(x1);
        __nv_bfloat16 h2 = __float2bfloat16(x2);
        vhi[o + d]      = h1;  vlo[o + d]      = __float2bfloat16(x1 - __bfloat162float(h1));
        vhi[o + d + 64] = h2;  vlo[o + d + 64] = __float2bfloat16(x2 - __bfloat162float(h2));
    }
}

// ---------------------------------------------------------------------------
// Flash attention v3 (round-14 verbatim — passing): 2 CTAs/SM,
// 64-row q-tiles, 32-row KV cp.async stages, longest-first scheduling.
// ---------------------------------------------------------------------------
#define FL3_STAGE      32768
#define FL3_SMEM_BYTES (32768 + 2 * FL3_STAGE)

__device__ __forceinline__ void fl3_kv_load(
    uint32_t st_base,
    const __nv_bfloat16* __restrict__ khi, const __nv_bfloat16* __restrict__ klo,
    const __nv_bfloat16* __restrict__ vhi, const __nv_bfloat16* __restrict__ vlo,
    int b, int g, int jt, int tid)
{
#pragma unroll
    for (int i = 0; i < 16; i++) {
        int lin = tid + 128 * i;          // 0..2047 16B units
        int sel = lin >> 9, rem = lin & 511;
        int r = rem >> 4, u = rem & 15;   // r: 0..31, u: 0..15
        const __nv_bfloat16* base =
            (sel == 0) ? khi : (sel == 1) ? klo : (sel == 2) ? vhi : vlo;
        const __nv_bfloat16* src =
            base + ((size_t)(b * SEQ + jt * 32 + r) * NKV + g) * HDIM + u * 8;
        uint32_t dst = st_base + sel * 8192 + r * 256 + ((u ^ (r & 7)) << 4);
        cp_async16(dst, src);
    }
    CP_COMMIT();
}

__global__ __launch_bounds__(128) void flash_mma3_kernel(
    const __nv_bfloat16* __restrict__ qhi, const __nv_bfloat16* __restrict__ qlo,
    const __nv_bfloat16* __restrict__ khi, const __nv_bfloat16* __restrict__ klo,
    const __nv_bfloat16* __restrict__ vhi, const __nv_bfloat16* __restrict__ vlo,
    __nv_bfloat16* __restrict__ out_hi, __nv_bfloat16* __restrict__ out_lo)
{
    extern __shared__ char sm[];
    const uint32_t smu = smem_u32(sm);
    const uint32_t sQh = smu;
    const uint32_t sQl = smu + 16384;

    const int tid  = threadIdx.x;
    const int wid  = tid >> 5;            // 0..3
    const int lane = tid & 31;

    const int qt = 31 - (blockIdx.x & 31);   // longest-first: 32 q-tiles of 64
    const int h  = (blockIdx.x >> 5) & 31;
    const int b  = blockIdx.x >> 10;
    const int g  = h >> 2;

    const int grp = lane >> 3, tt = lane & 7;
    const int rowA = tt + (grp & 1) * 8, duA = grp >> 1;
    const int rowB = tt + (grp >> 1) * 8, duB = grp & 1;
    const int rowV = tt + (grp & 1) * 8, dnV = grp >> 1;

    // ---- load Q tile (once): 64 rows hi+lo = 2048 x 16B over 128 threads
#pragma unroll
    for (int i = 0; i < 16; i++) {
        int lin = tid + 128 * i;
        int half = lin >> 10, rem = lin & 1023;
        int r = rem >> 4, u = rem & 15;
        const __nv_bfloat16* src = (half ? qlo : qhi) +
            ((size_t)(b * SEQ + qt * 64 + r) * NHEADS + h) * HDIM + u * 8;
        uint32_t doff = (half ? 16384 : 0) + r * 256 + ((u ^ (r & 7)) << 4);
        *(uint4*)(sm + doff) = *(const uint4*)src;
    }

    float m0 = -1e30f, m1 = -1e30f, l0 = 0.0f, l1 = 0.0f;
    float oacc[16][4];
#pragma unroll
    for (int i = 0; i < 16; i++)
#pragma unroll
        for (int r = 0; r < 4; r++) oacc[i][r] = 0.0f;

    const int njt = 2 * qt + 2;           // 32-row KV tiles
    fl3_kv_load(smu + 32768, khi, klo, vhi, vlo, b, g, 0, tid);

    for (int jt = 0; jt < njt; jt++) {
        asm volatile("cp.async.wait_group 0;" ::: "memory");
        __syncthreads();
        if (jt + 1 < njt)
            fl3_kv_load(smu + 32768 + ((jt + 1) & 1) * FL3_STAGE,
                        khi, klo, vhi, vlo, b, g, jt + 1, tid);

        const uint32_t st  = smu + 32768 + (jt & 1) * FL3_STAGE;
        const uint32_t sKh = st,          sKl = st + 8192;
        const uint32_t sVh = st + 16384,  sVl = st + 24576;

        // ---- S = Q K^T (warp: 16 q-rows x 32 k-cols)
        float sacc[4][4];
#pragma unroll
        for (int i = 0; i < 4; i++)
#pragma unroll
            for (int r = 0; r < 4; r++) sacc[i][r] = 0.0f;

#pragma unroll
        for (int ks = 0; ks < 8; ks++) {
            const int u0 = ks * 2;
            uint32_t aH[4], aL[4];
            {
                int row = wid * 16 + rowA;
                uint32_t off = row * 256 + (((u0 + duA) ^ (row & 7)) << 4);
                ldsm4(aH, sQh + off);
                ldsm4(aL, sQl + off);
            }
#pragma unroll
            for (int p = 0; p < 2; p++) {
                int row = p * 16 + rowB;
                uint32_t off = row * 256 + (((u0 + duB) ^ (row & 7)) << 4);
                uint32_t rh[4], rl[4];
                ldsm4(rh, sKh + off);
                ldsm4(rl, sKl + off);
                uint32_t bh0[2] = {rh[0], rh[1]}, bh1[2] = {rh[2], rh[3]};
                uint32_t bl0[2] = {rl[0], rl[1]}, bl1[2] = {rl[2], rl[3]};
                mma_bf16(sacc[2*p],   aH, bh0);
                mma_bf16(sacc[2*p],   aH, bl0);
                mma_bf16(sacc[2*p],   aL, bh0);
                mma_bf16(sacc[2*p+1], aH, bh1);
                mma_bf16(sacc[2*p+1], aH, bl1);
                mma_bf16(sacc[2*p+1], aL, bh1);
            }
        }

        // ---- causal mask (global indices; only tiles crossing the diagonal)
        {
            int rmin = qt * 64 + wid * 16;
            if (jt * 32 + 31 > rmin) {
                int r0 = rmin + (lane >> 2);
#pragma unroll
                for (int nt = 0; nt < 4; nt++) {
                    int col = jt * 32 + nt * 8 + (lane & 3) * 2;
                    if (col     > r0)     sacc[nt][0] = -1e30f;
                    if (col + 1 > r0)     sacc[nt][1] = -1e30f;
                    if (col     > r0 + 8) sacc[nt][2] = -1e30f;
                    if (col + 1 > r0 + 8) sacc[nt][3] = -1e30f;
                }
            }
        }

        // ---- online softmax (rows r0, r0+8; reduce over lane&3 group)
        float mx0 = -1e30f, mx1 = -1e30f;
#pragma unroll
        for (int nt = 0; nt < 4; nt++) {
            mx0 = fmaxf(mx0, fmaxf(sacc[nt][0], sacc[nt][1]));
            mx1 = fmaxf(mx1, fmaxf(sacc[nt][2], sacc[nt][3]));
        }
        mx0 = fmaxf(mx0, __shfl_xor_sync(0xffffffffu, mx0, 1));
        mx0 = fmaxf(mx0, __shfl_xor_sync(0xffffffffu, mx0, 2));
        mx1 = fmaxf(mx1, __shfl_xor_sync(0xffffffffu, mx1, 1));
        mx1 = fmaxf(mx1, __shfl_xor_sync(0xffffffffu, mx1, 2));
        float mn0 = fmaxf(m0, mx0), mn1 = fmaxf(m1, mx1);
        float corr0 = __expf(m0 - mn0), corr1 = __expf(m1 - mn1);
        m0 = mn0; m1 = mn1;

        float sum0 = 0.0f, sum1 = 0.0f;
#pragma unroll
        for (int nt = 0; nt < 4; nt++) {
            sacc[nt][0] = __expf(sacc[nt][0] - mn0);
            sacc[nt][1] = __expf(sacc[nt][1] - mn0);
            sacc[nt][2] = __expf(sacc[nt][2] - mn1);
            sacc[nt][3] = __expf(sacc[nt][3] - mn1);
            sum0 += sacc[nt][0] + sacc[nt][1];
            sum1 += sacc[nt][2] + sacc[nt][3];
        }
        sum0 += __shfl_xor_sync(0xffffffffu, sum0, 1);
        sum0 += __shfl_xor_sync(0xffffffffu, sum0, 2);
        sum1 += __shfl_xor_sync(0xffffffffu, sum1, 1);
        sum1 += __shfl_xor_sync(0xffffffffu, sum1, 2);
        l0 = l0 * corr0 + sum0;
        l1 = l1 * corr1 + sum1;

#pragma unroll
        for (int nt = 0; nt < 16; nt++) {
            oacc[nt][0] *= corr0; oacc[nt][1] *= corr0;
            oacc[nt][2] *= corr1; oacc[nt][3] *= corr1;
        }

        // ---- O += P V (P split hi/lo in registers, V via ldmatrix.trans)
#pragma unroll
        for (int kt = 0; kt < 2; kt++) {
            const float* sa = sacc[2*kt];
            const float* sb = sacc[2*kt+1];
            float h00 = __bfloat162float(__float2bfloat16(sa[0]));
            float h01 = __bfloat162float(__float2bfloat16(sa[1]));
            float h02 = __bfloat162float(__float2bfloat16(sa[2]));
            float h03 = __bfloat162float(__float2bfloat16(sa[3]));
            float h10 = __bfloat162float(__float2bfloat16(sb[0]));
            float h11 = __bfloat162float(__float2bfloat16(sb[1]));
            float h12 = __bfloat162float(__float2bfloat16(sb[2]));
            float h13 = __bfloat162float(__float2bfloat16(sb[3]));
            uint32_t ah[4], al[4];
            ah[0] = pack_bf16(h00, h01);  al[0] = pack_bf16(sa[0]-h00, sa[1]-h01);
            ah[1] = pack_bf16(h02, h03);  al[1] = pack_bf16(sa[2]-h02, sa[3]-h03);
            ah[2] = pack_bf16(h10, h11);  al[2] = pack_bf16(sb[0]-h10, sb[1]-h11);
            ah[3] = pack_bf16(h12, h13);  al[3] = pack_bf16(sb[2]-h12, sb[3]-h13);

#pragma unroll
            for (int nn = 0; nn < 8; nn++) {
                int row = kt * 16 + rowV;
                int u = nn * 2 + dnV;
                uint32_t off = row * 256 + ((u ^ (row & 7)) << 4);
                uint32_t rvh[4], rvl[4];
                ldsm4t(rvh, sVh + off);
                ldsm4t(rvl, sVl + off);
                uint32_t bh0[2] = {rvh[0], rvh[1]}, bh1[2] = {rvh[2], rvh[3]};
                uint32_t bl0[2] = {rvl[0], rvl[1]}, bl1[2] = {rvl[2], rvl[3]};
                mma_bf16(oacc[2*nn],   ah, bh0);
                mma_bf16(oacc[2*nn],   ah, bl0);
                mma_bf16(oacc[2*nn],   al, bh0);
                mma_bf16(oacc[2*nn+1], ah, bh1);
                mma_bf16(oacc[2*nn+1], ah, bl1);
                mma_bf16(oacc[2*nn+1], al, bh1);
            }
        }
    }

    // ---- epilogue: normalize, split bf16 hi/lo, write
    float inv0 = 1.0f / l0, inv1 = 1.0f / l1;
    size_t row0 = (size_t)(b * SEQ + qt * 64 + wid * 16 + (lane >> 2));
    size_t row1 = row0 + 8;
#pragma unroll
    for (int nt = 0; nt < 16; nt++) {
        int col = h * 128 + nt * 8 + (lane & 3) * 2;
        float v00 = oacc[nt][0] * inv0, v01 = oacc[nt][1] * inv0;
        float v10 = oacc[nt][2] * inv1, v11 = oacc[nt][3] * inv1;
        __nv_bfloat16 a0 = __float2bfloat16(v00), a1 = __float2bfloat16(v01);
        __nv_bfloat16 b0 = __float2bfloat16(v10), b1 = __float2bfloat16(v11);
        *(__nv_bfloat162*)(out_hi + row0 * HID + col) = __nv_bfloat162(a0, a1);
        *(__nv_bfloat162*)(out_lo + row0 * HID + col) = __nv_bfloat162(
            __float2bfloat16(v00 - __bfloat162float(a0)),
            __float2bfloat16(v01 - __bfloat162float(a1)));
        *(__nv_bfloat162*)(out_hi + row1 * HID + col) = __nv_bfloat162(b0, b1);
        *(__nv_bfloat162*)(out_lo + row1 * HID + col) = __nv_bfloat162(
            __float2bfloat16(v10 - __bfloat162float(b0)),
            __float2bfloat16(v11 - __bfloat162float(b1)));
    }
}

// ---------------------------------------------------------------------------
extern "C" void kernel_launch(void* const* d_in, const int* in_sizes, int n_in,
                              void* d_out, int out_size)
{
    const float* hidden    = (const float*)d_in[0];
    const int*   positions = (const int*)  d_in[1];
    const float* w_qkv     = (const float*)d_in[2];
    const float* w_o       = (const float*)d_in[3];
    float*       out       = (float*)d_out;

    float* qkv;
    cudaGetSymbolAddress((void**)&qkv, g_qkv);
    __nv_bfloat16 *hid_hi, *hid_lo, *wqkv_hi, *wqkv_lo;
    __nv_bfloat16 *attn_hi, *attn_lo, *wo_hi, *wo_lo;
    __nv_bfloat16 *q_hi, *q_lo, *k_hi, *k_lo, *v_hi, *v_lo;
    cudaGetSymbolAddress((void**)&hid_hi,  g_hid_hi);
    cudaGetSymbolAddress((void**)&hid_lo,  g_hid_lo);
    cudaGetSymbolAddress((void**)&wqkv_hi, g_wqkv_hi);
    cudaGetSymbolAddress((void**)&wqkv_lo, g_wqkv_lo);
    cudaGetSymbolAddress((void**)&attn_hi, g_attn_hi);
    cudaGetSymbolAddress((void**)&attn_lo, g_attn_lo);
    cudaGetSymbolAddress((void**)&wo_hi,   g_wo_hi);
    cudaGetSymbolAddress((void**)&wo_lo,   g_wo_lo);
    cudaGetSymbolAddress((void**)&q_hi,    g_q_hi);
    cudaGetSymbolAddress((void**)&q_lo,    g_q_lo);
    cudaGetSymbolAddress((void**)&k_hi,    g_k_hi);
    cudaGetSymbolAddress((void**)&k_lo,    g_k_lo);
    cudaGetSymbolAddress((void**)&v_hi,    g_v_hi);
    cudaGetSymbolAddress((void**)&v_lo,    g_v_lo);

    cudaFuncSetAttribute(mma_gemm_ca,
                         cudaFuncAttributeMaxDynamicSharedMemorySize,
                         GEMM_SMEM_BYTES);
    cudaFuncSetAttribute(flash_mma3_kernel,
                         cudaFuncAttributeMaxDynamicSharedMemorySize,
                         FL3_SMEM_BYTES);

    // 0) split inputs to bf16 hi/lo
    {
        size_t n_hid  = (size_t)MTOK * HID;
        size_t n_wqkv = (size_t)QKV_N * HID;
        size_t n_wo   = (size_t)HID * HID;
        split_bf16_kernel<<<(unsigned)(n_hid  / 1024), 256>>>(hidden, hid_hi,  hid_lo,  n_hid);
        split_bf16_kernel<<<(unsigned)(n_wqkv / 1024), 256>>>(w_qkv,  wqkv_hi, wqkv_lo, n_wqkv);
        split_bf16_kernel<<<(unsigned)(n_wo   / 1024), 256>>>(w_o,    wo_hi,   wo_lo,   n_wo);
    }

    // 1) qkv = hidden @ w_qkv^T  (GEMM v4: warp 32x64, 2 CTA/SM)
    mma_gemm_ca<<<dim3(QKV_N / 128, MTOK / 64), 128, GEMM_SMEM_BYTES>>>(
        hid_hi, hid_lo, wqkv_hi, wqkv_lo, qkv, MTOK, QKV_N, HID);

    // 2) RoPE + split q/k/v to bf16 hi/lo (q pre-scaled)
    rope_split_kernel<<<(BATCH * SEQ * 48 * 64) / 256, 256>>>(
        qkv, positions, q_hi, q_lo, k_hi, k_lo, v_hi, v_lo);

    // 3) causal GQA flash attention v3 (round-14 verbatim)
    flash_mma3_kernel<<<BATCH * NHEADS * (SEQ / 64), 128, FL3_SMEM_BYTES>>>(
        q_hi, q_lo, k_hi, k_lo, v_hi, v_lo, attn_hi, attn_lo);

    // 4) out = attn @ w_o^T (GEMM v4)
    mma_gemm_ca<<<dim3(HID / 128, MTOK / 64), 128, GEMM_SMEM_BYTES>>>(
        attn_hi, attn_lo, wo_hi, wo_lo, out, MTOK, HID, HID);
}

// round 16
// speedup vs baseline: 1.0938x; 1.0938x over previous
#include <cuda_runtime.h>
#include <cuda_bf16.h>
#include <cstdint>

// Problem constants
#define BATCH    2
#define SEQ      2048
#define HID      4096
#define NHEADS   32
#define NKV      8
#define HDIM     128
#define QKV_N    6144          // 32*128 + 8*128 + 8*128
#define MTOK     (BATCH*SEQ)   // 4096 token rows

// ---------------------------------------------------------------------------
// Scratch (device globals: allowed; no runtime allocation)
// ---------------------------------------------------------------------------
__device__ float g_qkv[(size_t)MTOK * QKV_N];    // fp32 qkv after projection

__device__ __nv_bfloat16 g_hid_hi[(size_t)MTOK * HID];
__device__ __nv_bfloat16 g_hid_lo[(size_t)MTOK * HID];
__device__ __nv_bfloat16 g_wqkv_hi[(size_t)QKV_N * HID];
__device__ __nv_bfloat16 g_wqkv_lo[(size_t)QKV_N * HID];
__device__ __nv_bfloat16 g_attn_hi[(size_t)MTOK * HID];
__device__ __nv_bfloat16 g_attn_lo[(size_t)MTOK * HID];
__device__ __nv_bfloat16 g_wo_hi[(size_t)HID * HID];
__device__ __nv_bfloat16 g_wo_lo[(size_t)HID * HID];

// rope'd q/k and v, split bf16 hi/lo
__device__ __nv_bfloat16 g_q_hi[(size_t)MTOK * NHEADS * HDIM];
__device__ __nv_bfloat16 g_q_lo[(size_t)MTOK * NHEADS * HDIM];
__device__ __nv_bfloat16 g_k_hi[(size_t)MTOK * NKV * HDIM];
__device__ __nv_bfloat16 g_k_lo[(size_t)MTOK * NKV * HDIM];
__device__ __nv_bfloat16 g_v_hi[(size_t)MTOK * NKV * HDIM];
__device__ __nv_bfloat16 g_v_lo[(size_t)MTOK * NKV * HDIM];

// ---------------------------------------------------------------------------
// mma.sync + ldmatrix + cp.async helpers (family-agnostic on .target sm_100)
// ---------------------------------------------------------------------------
__device__ __forceinline__ uint32_t smem_u32(const void* p) {
    uint32_t a;
    asm("{ .reg .u64 t; cvta.to.shared.u64 t, %1; cvt.u32.u64 %0, t; }"
        : "=r"(a) : "l"(p));
    return a;
}
__device__ __forceinline__ void ldsm4(uint32_t* r, uint32_t addr) {
    asm volatile("ldmatrix.sync.aligned.m8n8.x4.shared.b16 {%0,%1,%2,%3}, [%4];"
        : "=r"(r[0]), "=r"(r[1]), "=r"(r[2]), "=r"(r[3]) : "r"(addr));
}
__device__ __forceinline__ void ldsm4t(uint32_t* r, uint32_t addr) {
    asm volatile("ldmatrix.sync.aligned.m8n8.x4.trans.shared.b16 {%0,%1,%2,%3}, [%4];"
        : "=r"(r[0]), "=r"(r[1]), "=r"(r[2]), "=r"(r[3]) : "r"(addr));
}
__device__ __forceinline__ void mma_bf16(float* d, const uint32_t* a, const uint32_t* b) {
    asm volatile(
        "mma.sync.aligned.m16n8k16.row.col.f32.bf16.bf16.f32 "
        "{%0,%1,%2,%3}, {%4,%5,%6,%7}, {%8,%9}, {%0,%1,%2,%3};"
        : "+f"(d[0]), "+f"(d[1]), "+f"(d[2]), "+f"(d[3])
        : "r"(a[0]), "r"(a[1]), "r"(a[2]), "r"(a[3]), "r"(b[0]), "r"(b[1]));
}
__device__ __forceinline__ void cp_async16(uint32_t s, const void* g) {
    asm volatile("cp.async.cg.shared.global [%0], [%1], 16;" :: "r"(s), "l"(g));
}
#define CP_COMMIT() asm volatile("cp.async.commit_group;" ::: "memory")

__device__ __forceinline__ uint32_t pack_bf16(float x, float y) {
    __nv_bfloat162 t = __floats2bfloat162_rn(x, y);
    return *(uint32_t*)&t;
}

// ---------------------------------------------------------------------------
// Merged fp32 -> bf16 (hi, lo) splitter for all three inputs (one launch).
// ---------------------------------------------------------------------------
#define N_HID  ((size_t)MTOK * HID)       // 16777216
#define N_WQKV ((size_t)QKV_N * HID)      // 25165824
#define N_WO   ((size_t)HID * HID)        // 16777216
#define N_ALL  (N_HID + N_WQKV + N_WO)    // 58720256

__global__ __launch_bounds__(256) void split_all_kernel(
    const float* __restrict__ hid, const float* __restrict__ wqkv,
    const float* __restrict__ wo,
    __nv_bfloat16* __restrict__ hid_hi, __nv_bfloat16* __restrict__ hid_lo,
    __nv_bfloat16* __restrict__ wqkv_hi, __nv_bfloat16* __restrict__ wqkv_lo,
    __nv_bfloat16* __restrict__ wo_hi,  __nv_bfloat16* __restrict__ wo_lo)
{
    size_t i = ((size_t)blockIdx.x * blockDim.x + threadIdx.x) * 4;
    if (i >= N_ALL) return;
    const float* src;
    __nv_bfloat16 *hi, *lo;
    if (i < N_HID) {
        src = hid + i;              hi = hid_hi + i;             lo = hid_lo + i;
    } else if (i < N_HID + N_WQKV) {
        size_t j = i - N_HID;
        src = wqkv + j;             hi = wqkv_hi + j;            lo = wqkv_lo + j;
    } else {
        size_t j = i - N_HID - N_WQKV;
        src = wo + j;               hi = wo_hi + j;              lo = wo_lo + j;
    }
    float4 v = *(const float4*)src;
    float vs[4] = {v.x, v.y, v.z, v.w};
    __nv_bfloat16 h[4], l[4];
#pragma unroll
    for (int k = 0; k < 4; k++) {
        h[k] = __float2bfloat16(vs[k]);
        l[k] = __float2bfloat16(vs[k] - __bfloat162float(h[k]));
    }
    *(__nv_bfloat162*)(hi)     = __nv_bfloat162(h[0], h[1]);
    *(__nv_bfloat162*)(hi + 2) = __nv_bfloat162(h[2], h[3]);
    *(__nv_bfloat162*)(lo)     = __nv_bfloat162(l[0], l[1]);
    *(__nv_bfloat162*)(lo + 2) = __nv_bfloat162(l[2], l[3]);
}

// ---------------------------------------------------------------------------
// Tensor-core GEMM (round-12/14 verbatim — passing; plateau for HMMA path).
// CTA tile 128x64, K-chunk 64, 256 threads = 8 warps (4m x 2n), warp 32x32.
// 2-stage cp.async, 96KB -> 2 CTA/SM, 16 warps/SM.
// ---------------------------------------------------------------------------
#define GS_STAGE   49152
#define GEMM_SMEM_BYTES (2 * GS_STAGE)

__device__ __forceinline__ void gemm_stage_load(
    uint32_t stu,
    const __nv_bfloat16* __restrict__ gAhi, const __nv_bfloat16* __restrict__ gAlo,
    const __nv_bfloat16* __restrict__ gBhi, const __nv_bfloat16* __restrict__ gBlo,
    int K, int ko, int tid)
{
#pragma unroll
    for (int i = 0; i < 8; i++) {           // A tiles: 2048 x 16B
        int lin = tid + 256 * i;
        int tile = lin >> 10, rem = lin & 1023;
        int r = rem >> 3, u = rem & 7;
        const __nv_bfloat16* g = (tile ? gAlo : gAhi) + (size_t)r * K + ko + u * 8;
        cp_async16(stu + tile * 16384 + r * 128 + ((u ^ (r & 7)) << 4), g);
    }
#pragma unroll
    for (int i = 0; i < 4; i++) {           // B tiles: 1024 x 16B
        int lin = tid + 256 * i;
        int tile = lin >> 9, rem = lin & 511;
        int r = rem >> 3, u = rem & 7;
        const __nv_bfloat16* g = (tile ? gBlo : gBhi) + (size_t)r * K + ko + u * 8;
        cp_async16(stu + 32768 + tile * 8192 + r * 128 + ((u ^ (r & 7)) << 4), g);
    }
    CP_COMMIT();
}

__global__ __launch_bounds__(256) void mma_gemm_ca(
    const __nv_bfloat16* __restrict__ Ahi, const __nv_bfloat16* __restrict__ Alo,
    const __nv_bfloat16* __restrict__ Bhi, const __nv_bfloat16* __restrict__ Blo,
    float* __restrict__ C, int M, int N, int K)
{
    extern __shared__ char smem[];
    const uint32_t smem_u = smem_u32(smem);
    const int tid  = threadIdx.x;
    const int wid  = tid >> 5;
    const int lane = tid & 31;
    const int warp_m = wid & 3;
    const int warp_n = wid >> 2;

    const int bm = blockIdx.y * 128;
    const int bn = blockIdx.x * 64;

    const int grp = lane >> 3, tt = lane & 7;
    const int rowA = tt + (grp & 1) * 8, duA = grp >> 1;
    const int rowB = tt + (grp >> 1) * 8, duB = grp & 1;

    const __nv_bfloat16* gAhi = Ahi + (size_t)bm * K;
    const __nv_bfloat16* gAlo = Alo + (size_t)bm * K;
    const __nv_bfloat16* gBhi = Bhi + (size_t)bn * K;
    const __nv_bfloat16* gBlo = Blo + (size_t)bn * K;

    float acc[2][4][4];
#pragma unroll
    for (int i = 0; i < 2; i++)
#pragma unroll
        for (int j = 0; j < 4; j++)
#pragma unroll
            for (int r = 0; r < 4; r++) acc[i][j][r] = 0.0f;

    const int nch = K >> 6;
    gemm_stage_load(smem_u, gAhi, gAlo, gBhi, gBlo, K, 0, tid);

    for (int kc = 0; kc < nch; kc++) {
        asm volatile("cp.async.wait_group 0;" ::: "memory");
        __syncthreads();

        if (kc + 1 < nch)
            gemm_stage_load(smem_u + ((kc + 1) & 1) * GS_STAGE,
                            gAhi, gAlo, gBhi, gBlo, K, (kc + 1) << 6, tid);

        const uint32_t st  = smem_u + (kc & 1) * GS_STAGE;
        const uint32_t stAh = st,           stAl = st + 16384;
        const uint32_t stBh = st + 32768,   stBl = st + 40960;

#pragma unroll
        for (int ks = 0; ks < 4; ks++) {
            const int u0 = ks * 2;
            uint32_t aH[2][4], aL[2][4];
#pragma unroll
            for (int mt = 0; mt < 2; mt++) {
                int row = warp_m * 32 + mt * 16 + rowA;
                uint32_t off = row * 128 + (((u0 + duA) ^ (row & 7)) << 4);
                ldsm4(aH[mt], stAh + off);
                ldsm4(aL[mt], stAl + off);
            }
            uint32_t bH[4][2], bL[4][2];
#pragma unroll
            for (int p = 0; p < 2; p++) {
                int row = warp_n * 32 + p * 16 + rowB;
                uint32_t off = row * 128 + (((u0 + duB) ^ (row & 7)) << 4);
                uint32_t rh[4], rl[4];
                ldsm4(rh, stBh + off);
                ldsm4(rl, stBl + off);
                bH[2*p][0]=rh[0]; bH[2*p][1]=rh[1]; bH[2*p+1][0]=rh[2]; bH[2*p+1][1]=rh[3];
                bL[2*p][0]=rl[0]; bL[2*p][1]=rl[1]; bL[2*p+1][0]=rl[2]; bL[2*p+1][1]=rl[3];
            }
#pragma unroll
            for (int mt = 0; mt < 2; mt++)
#pragma unroll
                for (int nt = 0; nt < 4; nt++) {
                    mma_bf16(acc[mt][nt], aH[mt], bH[nt]);
                    mma_bf16(acc[mt][nt], aH[mt], bL[nt]);
                    mma_bf16(acc[mt][nt], aL[mt], bH[nt]);
                }
        }
    }

#pragma unroll
    for (int mt = 0; mt < 2; mt++) {
        int row = bm + warp_m * 32 + mt * 16 + (lane >> 2);
#pragma unroll
        for (int nt = 0; nt < 4; nt++) {
            int col = bn + warp_n * 32 + nt * 8 + (lane & 3) * 2;
            *(float2*)(C + (size_t)row * N + col) =
                make_float2(acc[mt][nt][0], acc[mt][nt][1]);
            *(float2*)(C + (size_t)(row + 8) * N + col) =
                make_float2(acc[mt][nt][2], acc[mt][nt][3]);
        }
    }
}

// ---------------------------------------------------------------------------
// RoPE + split (fast-math: __expf / __sincosf — precision bound measured in
// round 10: rel_err 7.47e-5). Reads fp32 g_qkv, writes bf16 hi/lo q/k/v.
// ---------------------------------------------------------------------------
__global__ __launch_bounds__(256) void rope_split_kernel(
    const float* __restrict__ qkv, const int* __restrict__ positions,
    __nv_bfloat16* __restrict__ qhi, __nv_bfloat16* __restrict__ qlo,
    __nv_bfloat16* __restrict__ khi, __nv_bfloat16* __restrict__ klo,
    __nv_bfloat16* __restrict__ vhi, __nv_bfloat16* __restrict__ vlo)
{
    int idx  = blockIdx.x * blockDim.x + threadIdx.x;
    int d    = idx & 63;
    int t    = idx >> 6;
    int head = t % 48;
    int tok  = t / 48;
    const float scale = 0.08838834764831845f;   // 1/sqrt(128)

    if (head < 40) {
        float pos = (float)positions[tok];
        float freq = pos * __expf(-(float)d * 0.21586735246819178f);
        float s, c;
        __sincosf(freq, &s, &c);
        const float* p = qkv + (size_t)tok * QKV_N +
                         (head < 32 ? head * 128 : 4096 + (head - 32) * 128);
        float x1 = p[d], x2 = p[d + 64];
        float r1 = x1 * c - x2 * s;
        float r2 = x2 * c + x1 * s;
        __nv_bfloat16 *dh, *dl;
        if (head < 32) {
            r1 *= scale; r2 *= scale;
            size_t o = ((size_t)tok * NHEADS + head) * HDIM;
            dh = qhi + o; dl = qlo + o;
        } else {
            size_t o = ((size_t)tok * NKV + (head - 32)) * HDIM;
            dh = khi + o; dl = klo + o;
        }
        __nv_bfloat16 h1 = __float2bfloat16(r1);
        __nv_bfloat16 h2 = __float2bfloat16(r2);
        dh[d]      = h1;  dl[d]      = __float2bfloat16(r1 - __bfloat162float(h1));
        dh[d + 64] = h2;  dl[d + 64] = __float2bfloat16(r2 - __bfloat162float(h2));
    } else {
        int gk = head - 40;
        const float* p = qkv + (size_t)tok * QKV_N + 5120 + gk * 128;
        size_t o = ((size_t)tok * NKV + gk) * HDIM;
        float x1 = p[d], x2 = p[d + 64];
        __nv_bfloat16 h1 = __float2bfloat16(x1);
        __nv_bfloat16 h2 = __float2bfloat16(x2);
        vhi[o + d]      = h1;  vlo[o + d]      = __float2bfloat16(x1 - __bfloat162float(h1));
        vhi[o + d + 64] = h2;  vlo[o + d + 64] = __float2bfloat16(x2 - __bfloat162float(h2));
    }
}

// ---------------------------------------------------------------------------
// Flash attention v3 (round-14 base): 2 CTAs/SM, 64-row q-tiles, 32-row KV
// cp.async stages, longest-first scheduling. One change: KV stage-0 prefetch
// issued BEFORE the synchronous Q load (independent smem regions).
// ---------------------------------------------------------------------------
#define FL3_STAGE      32768
#define FL3_SMEM_BYTES (32768 + 2 * FL3_STAGE)

__device__ __forceinline__ void fl3_kv_load(
    uint32_t st_base,
    const __nv_bfloat16* __restrict__ khi, const __nv_bfloat16* __restrict__ klo,
    const __nv_bfloat16* __restrict__ vhi, const __nv_bfloat16* __restrict__ vlo,
    int b, int g, int jt, int tid)
{
#pragma unroll
    for (int i = 0; i < 16; i++) {
        int lin = tid + 128 * i;          // 0..2047 16B units
        int sel = lin >> 9, rem = lin & 511;
        int r = rem >> 4, u = rem & 15;   // r: 0..31, u: 0..15
        const __nv_bfloat16* base =
            (sel == 0) ? khi : (sel == 1) ? klo : (sel == 2) ? vhi : vlo;
        const __nv_bfloat16* src =
            base + ((size_t)(b * SEQ + jt * 32 + r) * NKV + g) * HDIM + u * 8;
        uint32_t dst = st_base + sel * 8192 + r * 256 + ((u ^ (r & 7)) << 4);
        cp_async16(dst, src);
    }
    CP_COMMIT();
}

__global__ __launch_bounds__(128) void flash_mma3_kernel(
    const __nv_bfloat16* __restrict__ qhi, const __nv_bfloat16* __restrict__ qlo,
    const __nv_bfloat16* __restrict__ khi, const __nv_bfloat16* __restrict__ klo,
    const __nv_bfloat16* __restrict__ vhi, const __nv_bfloat16* __restrict__ vlo,
    __nv_bfloat16* __restrict__ out_hi, __nv_bfloat16* __restrict__ out_lo)
{
    extern __shared__ char sm[];
    const uint32_t smu = smem_u32(sm);
    const uint32_t sQh = smu;
    const uint32_t sQl = smu + 16384;

    const int tid  = threadIdx.x;
    const int wid  = tid >> 5;            // 0..3
    const int lane = tid & 31;

    const int qt = 31 - (blockIdx.x & 31);   // longest-first: 32 q-tiles of 64
    const int h  = (blockIdx.x >> 5) & 31;
    const int b  = blockIdx.x >> 10;
    const int g  = h >> 2;

    const int grp = lane >> 3, tt = lane & 7;
    const int rowA = tt + (grp & 1) * 8, duA = grp >> 1;
    const int rowB = tt + (grp >> 1) * 8, duB = grp & 1;
    const int rowV = tt + (grp & 1) * 8, dnV = grp >> 1;

    // ---- KV stage-0 prefetch first (async; independent of Q smem region)
    fl3_kv_load(smu + 32768, khi, klo, vhi, vlo, b, g, 0, tid);

    // ---- load Q tile (once): 64 rows hi+lo = 2048 x 16B over 128 threads
#pragma unroll
    for (int i = 0; i < 16; i++) {
        int lin = tid + 128 * i;
        int half = lin >> 10, rem = lin & 1023;
        int r = rem >> 4, u = rem & 15;
        const __nv_bfloat16* src = (half ? qlo : qhi) +
            ((size_t)(b * SEQ + qt * 64 + r) * NHEADS + h) * HDIM + u * 8;
        uint32_t doff = (half ? 16384 : 0) + r * 256 + ((u ^ (r & 7)) << 4);
        *(uint4*)(sm + doff) = *(const uint4*)src;
    }

    float m0 = -1e30f, m1 = -1e30f, l0 = 0.0f, l1 = 0.0f;
    float oacc[16][4];
#pragma unroll
    for (int i = 0; i < 16; i++)
#pragma unroll
        for (int r = 0; r < 4; r++) oacc[i][r] = 0.0f;

    const int njt = 2 * qt + 2;           // 32-row KV tiles

    for (int jt = 0; jt < njt; jt++) {
        asm volatile("cp.async.wait_group 0;" ::: "memory");
        __syncthreads();
        if (jt + 1 < njt)
            fl3_kv_load(smu + 32768 + ((jt + 1) & 1) * FL3_STAGE,
                        khi, klo, vhi, vlo, b, g, jt + 1, tid);

        const uint32_t st  = smu + 32768 + (jt & 1) * FL3_STAGE;
        const uint32_t sKh = st,          sKl = st + 8192;
        const uint32_t sVh = st + 16384,  sVl = st + 24576;

        // ---- S = Q K^T (warp: 16 q-rows x 32 k-cols)
        float sacc[4][4];
#pragma unroll
        for (int i = 0; i < 4; i++)
#pragma unroll
            for (int r = 0; r < 4; r++) sacc[i][r] = 0.0f;

#pragma unroll
        for (int ks = 0; ks < 8; ks++) {
            const int u0 = ks * 2;
            uint32_t aH[4], aL[4];
            {
                int row = wid * 16 + rowA;
                uint32_t off = row * 256 + (((u0 + duA) ^ (row & 7)) << 4);
                ldsm4(aH, sQh + off);
                ldsm4(aL, sQl + off);
            }
#pragma unroll
            for (int p = 0; p < 2; p++) {
                int row = p * 16 + rowB;
                uint32_t off = row * 256 + (((u0 + duB) ^ (row & 7)) << 4);
                uint32_t rh[4], rl[4];
                ldsm4(rh, sKh + off);
                ldsm4(rl, sKl + off);
                uint32_t bh0[2] = {rh[0], rh[1]}, bh1[2] = {rh[2], rh[3]};
                uint32_t bl0[2] = {rl[0], rl[1]}, bl1[2] = {rl[2], rl[3]};
                mma_bf16(sacc[2*p],   aH, bh0);
                mma_bf16(sacc[2*p],   aH, bl0);
                mma_bf16(sacc[2*p],   aL, bh0);
                mma_bf16(sacc[2*p+1], aH, bh1);
                mma_bf16(sacc[2*p+1], aH, bl1);
                mma_bf16(sacc[2*p+1], aL, bh1);
            }
        }

        // ---- causal mask (global indices; only tiles crossing the diagonal)
        {
            int rmin = qt * 64 + wid * 16;
            if (jt * 32 + 31 > rmin) {
                int r0 = rmin + (lane >> 2);
#pragma unroll
                for (int nt = 0; nt < 4; nt++) {
                    int col = jt * 32 + nt * 8 + (lane & 3) * 2;
                    if (col     > r0)     sacc[nt][0] = -1e30f;
                    if (col + 1 > r0)     sacc[nt][1] = -1e30f;
                    if (col     > r0 + 8) sacc[nt][2] = -1e30f;
                    if (col + 1 > r0 + 8) sacc[nt][3] = -1e30f;
                }
            }
        }

        // ---- online softmax (rows r0, r0+8; reduce over lane&3 group)
        float mx0 = -1e30f, mx1 = -1e30f;
#pragma unroll
        for (int nt = 0; nt < 4; nt++) {
            mx0 = fmaxf(mx0, fmaxf(sacc[nt][0], sacc[nt][1]));
            mx1 = fmaxf(mx1, fmaxf(sacc[nt][2], sacc[nt][3]));
        }
        mx0 = fmaxf(mx0, __shfl_xor_sync(0xffffffffu, mx0, 1));
        mx0 = fmaxf(mx0, __shfl_xor_sync(0xffffffffu, mx0, 2));
        mx1 = fmaxf(mx1, __shfl_xor_sync(0xffffffffu, mx1, 1));
        mx1 = fmaxf(mx1, __shfl_xor_sync(0xffffffffu, mx1, 2));
        float mn0 = fmaxf(m0, mx0), mn1 = fmaxf(m1, mx1);
        float corr0 = __expf(m0 - mn0), corr1 = __expf(m1 - mn1);
        m0 = mn0; m1 = mn1;

        float sum0 = 0.0f, sum1 = 0.0f;
#pragma unroll
        for (int nt = 0; nt < 4; nt++) {
            sacc[nt][0] = __expf(sacc[nt][0] - mn0);
            sacc[nt][1] = __expf(sacc[nt][1] - mn0);
            sacc[nt][2] = __expf(sacc[nt][2] - mn1);
            sacc[nt][3] = __expf(sacc[nt][3] - mn1);
            sum0 += sacc[nt][0] + sacc[nt][1];
            sum1 += sacc[nt][2] + sacc[nt][3];
        }
        sum0 += __shfl_xor_sync(0xffffffffu, sum0, 1);
        sum0 += __shfl_xor_sync(0xffffffffu, sum0, 2);
        sum1 += __shfl_xor_sync(0xffffffffu, sum1, 1);
        sum1 += __shfl_xor_sync(0xffffffffu, sum1, 2);
        l0 = l0 * corr0 + sum0;
        l1 = l1 * corr1 + sum1;

#pragma unroll
        for (int nt = 0; nt < 16; nt++) {
            oacc[nt][0] *= corr0; oacc[nt][1] *= corr0;
            oacc[nt][2] *= corr1; oacc[nt][3] *= corr1;
        }

        // ---- O += P V (P split hi/lo in registers, V via ldmatrix.trans)
#pragma unroll
        for (int kt = 0; kt < 2; kt++) {
            const float* sa = sacc[2*kt];
            const float* sb = sacc[2*kt+1];
            float h00 = __bfloat162float(__float2bfloat16(sa[0]));
            float h01 = __bfloat162float(__float2bfloat16(sa[1]));
            float h02 = __bfloat162float(__float2bfloat16(sa[2]));
            float h03 = __bfloat162float(__float2bfloat16(sa[3]));
            float h10 = __bfloat162float(__float2bfloat16(sb[0]));
            float h11 = __bfloat162float(__float2bfloat16(sb[1]));
            float h12 = __bfloat162float(__float2bfloat16(sb[2]));
            float h13 = __bfloat162float(__float2bfloat16(sb[3]));
            uint32_t ah[4], al[4];
            ah[0] = pack_bf16(h00, h01);  al[0] = pack_bf16(sa[0]-h00, sa[1]-h01);
            ah[1] = pack_bf16(h02, h03);  al[1] = pack_bf16(sa[2]-h02, sa[3]-h03);
            ah[2] = pack_bf16(h10, h11);  al[2] = pack_bf16(sb[0]-h10, sb[1]-h11);
            ah[3] = pack_bf16(h12, h13);  al[3] = pack_bf16(sb[2]-h12, sb[3]-h13);

#pragma unroll
            for (int nn = 0; nn < 8; nn++) {
                int row = kt * 16 + rowV;
                int u = nn * 2 + dnV;
                uint32_t off = row * 256 + ((u ^ (row & 7)) << 4);
                uint32_t rvh[4], rvl[4];
                ldsm4t(rvh, sVh + off);
                ldsm4t(rvl, sVl + off);
                uint32_t bh0[2] = {rvh[0], rvh[1]}, bh1[2] = {rvh[2], rvh[3]};
                uint32_t bl0[2] = {rvl[0], rvl[1]}, bl1[2] = {rvl[2], rvl[3]};
                mma_bf16(oacc[2*nn],   ah, bh0);
                mma_bf16(oacc[2*nn],   ah, bl0);
                mma_bf16(oacc[2*nn],   al, bh0);
                mma_bf16(oacc[2*nn+1], ah, bh1);
                mma_bf16(oacc[2*nn+1], ah, bl1);
                mma_bf16(oacc[2*nn+1], al, bh1);
            }
        }
    }

    // ---- epilogue: normalize, split bf16 hi/lo, write
    float inv0 = 1.0f / l0, inv1 = 1.0f / l1;
    size_t row0 = (size_t)(b * SEQ + qt * 64 + wid * 16 + (lane >> 2));
    size_t row1 = row0 + 8;
#pragma unroll
    for (int nt = 0; nt < 16; nt++) {
        int col = h * 128 + nt * 8 + (lane & 3) * 2;
        float v00 = oacc[nt][0] * inv0, v01 = oacc[nt][1] * inv0;
        float v10 = oacc[nt][2] * inv1, v11 = oacc[nt][3] * inv1;
        __nv_bfloat16 a0 = __float2bfloat16(v00), a1 = __float2bfloat16(v01);
        __nv_bfloat16 b0 = __float2bfloat16(v10), b1 = __float2bfloat16(v11);
        *(__nv_bfloat162*)(out_hi + row0 * HID + col) = __nv_bfloat162(a0, a1);
        *(__nv_bfloat162*)(out_lo + row0 * HID + col) = __nv_bfloat162(
            __float2bfloat16(v00 - __bfloat162float(a0)),
            __float2bfloat16(v01 - __bfloat162float(a1)));
        *(__nv_bfloat162*)(out_hi + row1 * HID + col) = __nv_bfloat162(b0, b1);
        *(__nv_bfloat162*)(out_lo + row1 * HID + col) = __nv_bfloat162(
            __float2bfloat16(v10 - __bfloat162float(b0)),
            __float2bfloat16(v11 - __bfloat162float(b1)));
    }
}

// ---------------------------------------------------------------------------
extern "C" void kernel_launch(void* const* d_in, const int* in_sizes, int n_in,
                              void* d_out, int out_size)
{
    const float* hidden    = (const float*)d_in[0];
    const int*   positions = (const int*)  d_in[1];
    const float* w_qkv     = (const float*)d_in[2];
    const float* w_o       = (const float*)d_in[3];
    float*       out       = (float*)d_out;

    float* qkv;
    cudaGetSymbolAddress((void**)&qkv, g_qkv);
    __nv_bfloat16 *hid_hi, *hid_lo, *wqkv_hi, *wqkv_lo;
    __nv_bfloat16 *attn_hi, *attn_lo, *wo_hi, *wo_lo;
    __nv_bfloat16 *q_hi, *q_lo, *k_hi, *k_lo, *v_hi, *v_lo;
    cudaGetSymbolAddress((void**)&hid_hi,  g_hid_hi);
    cudaGetSymbolAddress((void**)&hid_lo,  g_hid_lo);
    cudaGetSymbolAddress((void**)&wqkv_hi, g_wqkv_hi);
    cudaGetSymbolAddress((void**)&wqkv_lo, g_wqkv_lo);
    cudaGetSymbolAddress((void**)&attn_hi, g_attn_hi);
    cudaGetSymbolAddress((void**)&attn_lo, g_attn_lo);
    cudaGetSymbolAddress((void**)&wo_hi,   g_wo_hi);
    cudaGetSymbolAddress((void**)&wo_lo,   g_wo_lo);
    cudaGetSymbolAddress((void**)&q_hi,    g_q_hi);
    cudaGetSymbolAddress((void**)&q_lo,    g_q_lo);
    cudaGetSymbolAddress((void**)&k_hi,    g_k_hi);
    cudaGetSymbolAddress((void**)&k_lo,    g_k_lo);
    cudaGetSymbolAddress((void**)&v_hi,    g_v_hi);
    cudaGetSymbolAddress((void**)&v_lo,    g_v_lo);

    cudaFuncSetAttribute(mma_gemm_ca,
                         cudaFuncAttributeMaxDynamicSharedMemorySize,
                         GEMM_SMEM_BYTES);
    cudaFuncSetAttribute(flash_mma3_kernel,
                         cudaFuncAttributeMaxDynamicSharedMemorySize,
                         FL3_SMEM_BYTES);

    // 0) split all three fp32 inputs to bf16 hi/lo in one launch
    split_all_kernel<<<(unsigned)(N_ALL / 1024), 256>>>(
        hidden, w_qkv, w_o,
        hid_hi, hid_lo, wqkv_hi, wqkv_lo, wo_hi, wo_lo);

    // 1) qkv = hidden @ w_qkv^T  (tensor cores, cp.async pipelined)
    mma_gemm_ca<<<dim3(QKV_N / 64, MTOK / 128), 256, GEMM_SMEM_BYTES>>>(
        hid_hi, hid_lo, wqkv_hi, wqkv_lo, qkv, MTOK, QKV_N, HID);

    // 2) RoPE + split q/k/v to bf16 hi/lo (q pre-scaled, fast-math)
    rope_split_kernel<<<(BATCH * SEQ * 48 * 64) / 256, 256>>>(
        qkv, positions, q_hi, q_lo, k_hi, k_lo, v_hi, v_lo);

    // 3) causal GQA flash attention v3 (round-14 base + Q/KV load overlap)
    flash_mma3_kernel<<<BATCH * NHEADS * (SEQ / 64), 128, FL3_SMEM_BYTES>>>(
        q_hi, q_lo, k_hi, k_lo, v_hi, v_lo, attn_hi, attn_lo);

    // 4) out = attn @ w_o^T (tensor cores, cp.async pipelined)
    mma_gemm_ca<<<dim3(HID / 64, MTOK / 128), 256, GEMM_SMEM_BYTES>>>(
        attn_hi, attn_lo, wo_hi, wo_lo, out, MTOK, HID, HID);
}

// round 17
// speedup vs baseline: 1.1006x; 1.0062x over previous
#include <cuda_runtime.h>
#include <cuda_bf16.h>
#include <cstdint>

// Problem constants
#define BATCH    2
#define SEQ      2048
#define HID      4096
#define NHEADS   32
#define NKV      8
#define HDIM     128
#define QKV_N    6144          // 32*128 + 8*128 + 8*128
#define MTOK     (BATCH*SEQ)   // 4096 token rows

// ---------------------------------------------------------------------------
// Scratch (device globals: allowed; no runtime allocation)
// ---------------------------------------------------------------------------
__device__ float g_qkv[(size_t)MTOK * QKV_N];    // fp32 qkv after projection

__device__ __nv_bfloat16 g_hid_hi[(size_t)MTOK * HID];
__device__ __nv_bfloat16 g_hid_lo[(size_t)MTOK * HID];
__device__ __nv_bfloat16 g_wqkv_hi[(size_t)QKV_N * HID];
__device__ __nv_bfloat16 g_wqkv_lo[(size_t)QKV_N * HID];
__device__ __nv_bfloat16 g_attn_hi[(size_t)MTOK * HID];
__device__ __nv_bfloat16 g_attn_lo[(size_t)MTOK * HID];
__device__ __nv_bfloat16 g_wo_hi[(size_t)HID * HID];
__device__ __nv_bfloat16 g_wo_lo[(size_t)HID * HID];

// rope'd q/k and v, split bf16 hi/lo
__device__ __nv_bfloat16 g_q_hi[(size_t)MTOK * NHEADS * HDIM];
__device__ __nv_bfloat16 g_q_lo[(size_t)MTOK * NHEADS * HDIM];
__device__ __nv_bfloat16 g_k_hi[(size_t)MTOK * NKV * HDIM];
__device__ __nv_bfloat16 g_k_lo[(size_t)MTOK * NKV * HDIM];
__device__ __nv_bfloat16 g_v_hi[(size_t)MTOK * NKV * HDIM];
__device__ __nv_bfloat16 g_v_lo[(size_t)MTOK * NKV * HDIM];

// ---------------------------------------------------------------------------
// mma.sync + ldmatrix + cp.async helpers (family-agnostic on .target sm_100)
// ---------------------------------------------------------------------------
__device__ __forceinline__ uint32_t smem_u32(const void* p) {
    uint32_t a;
    asm("{ .reg .u64 t; cvta.to.shared.u64 t, %1; cvt.u32.u64 %0, t; }"
        : "=r"(a) : "l"(p));
    return a;
}
__device__ __forceinline__ void ldsm4(uint32_t* r, uint32_t addr) {
    asm volatile("ldmatrix.sync.aligned.m8n8.x4.shared.b16 {%0,%1,%2,%3}, [%4];"
        : "=r"(r[0]), "=r"(r[1]), "=r"(r[2]), "=r"(r[3]) : "r"(addr));
}
__device__ __forceinline__ void ldsm4t(uint32_t* r, uint32_t addr) {
    asm volatile("ldmatrix.sync.aligned.m8n8.x4.trans.shared.b16 {%0,%1,%2,%3}, [%4];"
        : "=r"(r[0]), "=r"(r[1]), "=r"(r[2]), "=r"(r[3]) : "r"(addr));
}
__device__ __forceinline__ void mma_bf16(float* d, const uint32_t* a, const uint32_t* b) {
    asm volatile(
        "mma.sync.aligned.m16n8k16.row.col.f32.bf16.bf16.f32 "
        "{%0,%1,%2,%3}, {%4,%5,%6,%7}, {%8,%9}, {%0,%1,%2,%3};"
        : "+f"(d[0]), "+f"(d[1]), "+f"(d[2]), "+f"(d[3])
        : "r"(a[0]), "r"(a[1]), "r"(a[2]), "r"(a[3]), "r"(b[0]), "r"(b[1]));
}
__device__ __forceinline__ void cp_async16(uint32_t s, const void* g) {
    asm volatile("cp.async.cg.shared.global [%0], [%1], 16;" :: "r"(s), "l"(g));
}
#define CP_COMMIT() asm volatile("cp.async.commit_group;" ::: "memory")

__device__ __forceinline__ uint32_t pack_bf16(float x, float y) {
    __nv_bfloat162 t = __floats2bfloat162_rn(x, y);
    return *(uint32_t*)&t;
}

// ---------------------------------------------------------------------------
// Merged fp32 -> bf16 (hi, lo) splitter for all three inputs (one launch).
// ---------------------------------------------------------------------------
#define N_HID  ((size_t)MTOK * HID)
#define N_WQKV ((size_t)QKV_N * HID)
#define N_WO   ((size_t)HID * HID)
#define N_ALL  (N_HID + N_WQKV + N_WO)

__global__ __launch_bounds__(256) void split_all_kernel(
    const float* __restrict__ hid, const float* __restrict__ wqkv,
    const float* __restrict__ wo,
    __nv_bfloat16* __restrict__ hid_hi, __nv_bfloat16* __restrict__ hid_lo,
    __nv_bfloat16* __restrict__ wqkv_hi, __nv_bfloat16* __restrict__ wqkv_lo,
    __nv_bfloat16* __restrict__ wo_hi,  __nv_bfloat16* __restrict__ wo_lo)
{
    size_t i = ((size_t)blockIdx.x * blockDim.x + threadIdx.x) * 4;
    if (i >= N_ALL) return;
    const float* src;
    __nv_bfloat16 *hi, *lo;
    if (i < N_HID) {
        src = hid + i;              hi = hid_hi + i;             lo = hid_lo + i;
    } else if (i < N_HID + N_WQKV) {
        size_t j = i - N_HID;
        src = wqkv + j;             hi = wqkv_hi + j;            lo = wqkv_lo + j;
    } else {
        size_t j = i - N_HID - N_WQKV;
        src = wo + j;               hi = wo_hi + j;              lo = wo_lo + j;
    }
    float4 v = *(const float4*)src;
    float vs[4] = {v.x, v.y, v.z, v.w};
    __nv_bfloat16 h[4], l[4];
#pragma unroll
    for (int k = 0; k < 4; k++) {
        h[k] = __float2bfloat16(vs[k]);
        l[k] = __float2bfloat16(vs[k] - __bfloat162float(h[k]));
    }
    *(__nv_bfloat162*)(hi)     = __nv_bfloat162(h[0], h[1]);
    *(__nv_bfloat162*)(hi + 2) = __nv_bfloat162(h[2], h[3]);
    *(__nv_bfloat162*)(lo)     = __nv_bfloat162(l[0], l[1]);
    *(__nv_bfloat162*)(lo + 2) = __nv_bfloat162(l[2], l[3]);
}

// ---------------------------------------------------------------------------
// Tensor-core GEMM (round-16 verbatim — passing; HMMA-path plateau ~82%).
// ---------------------------------------------------------------------------
#define GS_STAGE   49152
#define GEMM_SMEM_BYTES (2 * GS_STAGE)

__device__ __forceinline__ void gemm_stage_load(
    uint32_t stu,
    const __nv_bfloat16* __restrict__ gAhi, const __nv_bfloat16* __restrict__ gAlo,
    const __nv_bfloat16* __restrict__ gBhi, const __nv_bfloat16* __restrict__ gBlo,
    int K, int ko, int tid)
{
#pragma unroll
    for (int i = 0; i < 8; i++) {           // A tiles: 2048 x 16B
        int lin = tid + 256 * i;
        int tile = lin >> 10, rem = lin & 1023;
        int r = rem >> 3, u = rem & 7;
        const __nv_bfloat16* g = (tile ? gAlo : gAhi) + (size_t)r * K + ko + u * 8;
        cp_async16(stu + tile * 16384 + r * 128 + ((u ^ (r & 7)) << 4), g);
    }
#pragma unroll
    for (int i = 0; i < 4; i++) {           // B tiles: 1024 x 16B
        int lin = tid + 256 * i;
        int tile = lin >> 9, rem = lin & 511;
        int r = rem >> 3, u = rem & 7;
        const __nv_bfloat16* g = (tile ? gBlo : gBhi) + (size_t)r * K + ko + u * 8;
        cp_async16(stu + 32768 + tile * 8192 + r * 128 + ((u ^ (r & 7)) << 4), g);
    }
    CP_COMMIT();
}

__global__ __launch_bounds__(256) void mma_gemm_ca(
    const __nv_bfloat16* __restrict__ Ahi, const __nv_bfloat16* __restrict__ Alo,
    const __nv_bfloat16* __restrict__ Bhi, const __nv_bfloat16* __restrict__ Blo,
    float* __restrict__ C, int M, int N, int K)
{
    extern __shared__ char smem[];
    const uint32_t smem_u = smem_u32(smem);
    const int tid  = threadIdx.x;
    const int wid  = tid >> 5;
    const int lane = tid & 31;
    const int warp_m = wid & 3;
    const int warp_n = wid >> 2;

    const int bm = blockIdx.y * 128;
    const int bn = blockIdx.x * 64;

    const int grp = lane >> 3, tt = lane & 7;
    const int rowA = tt + (grp & 1) * 8, duA = grp >> 1;
    const int rowB = tt + (grp >> 1) * 8, duB = grp & 1;

    const __nv_bfloat16* gAhi = Ahi + (size_t)bm * K;
    const __nv_bfloat16* gAlo = Alo + (size_t)bm * K;
    const __nv_bfloat16* gBhi = Bhi + (size_t)bn * K;
    const __nv_bfloat16* gBlo = Blo + (size_t)bn * K;

    float acc[2][4][4];
#pragma unroll
    for (int i = 0; i < 2; i++)
#pragma unroll
        for (int j = 0; j < 4; j++)
#pragma unroll
            for (int r = 0; r < 4; r++) acc[i][j][r] = 0.0f;

    const int nch = K >> 6;
    gemm_stage_load(smem_u, gAhi, gAlo, gBhi, gBlo, K, 0, tid);

    for (int kc = 0; kc < nch; kc++) {
        asm volatile("cp.async.wait_group 0;" ::: "memory");
        __syncthreads();

        if (kc + 1 < nch)
            gemm_stage_load(smem_u + ((kc + 1) & 1) * GS_STAGE,
                            gAhi, gAlo, gBhi, gBlo, K, (kc + 1) << 6, tid);

        const uint32_t st  = smem_u + (kc & 1) * GS_STAGE;
        const uint32_t stAh = st,           stAl = st + 16384;
        const uint32_t stBh = st + 32768,   stBl = st + 40960;

#pragma unroll
        for (int ks = 0; ks < 4; ks++) {
            const int u0 = ks * 2;
            uint32_t aH[2][4], aL[2][4];
#pragma unroll
            for (int mt = 0; mt < 2; mt++) {
                int row = warp_m * 32 + mt * 16 + rowA;
                uint32_t off = row * 128 + (((u0 + duA) ^ (row & 7)) << 4);
                ldsm4(aH[mt], stAh + off);
                ldsm4(aL[mt], stAl + off);
            }
            uint32_t bH[4][2], bL[4][2];
#pragma unroll
            for (int p = 0; p < 2; p++) {
                int row = warp_n * 32 + p * 16 + rowB;
                uint32_t off = row * 128 + (((u0 + duB) ^ (row & 7)) << 4);
                uint32_t rh[4], rl[4];
                ldsm4(rh, stBh + off);
                ldsm4(rl, stBl + off);
                bH[2*p][0]=rh[0]; bH[2*p][1]=rh[1]; bH[2*p+1][0]=rh[2]; bH[2*p+1][1]=rh[3];
                bL[2*p][0]=rl[0]; bL[2*p][1]=rl[1]; bL[2*p+1][0]=rl[2]; bL[2*p+1][1]=rl[3];
            }
#pragma unroll
            for (int mt = 0; mt < 2; mt++)
#pragma unroll
                for (int nt = 0; nt < 4; nt++) {
                    mma_bf16(acc[mt][nt], aH[mt], bH[nt]);
                    mma_bf16(acc[mt][nt], aH[mt], bL[nt]);
                    mma_bf16(acc[mt][nt], aL[mt], bH[nt]);
                }
        }
    }

#pragma unroll
    for (int mt = 0; mt < 2; mt++) {
        int row = bm + warp_m * 32 + mt * 16 + (lane >> 2);
#pragma unroll
        for (int nt = 0; nt < 4; nt++) {
            int col = bn + warp_n * 32 + nt * 8 + (lane & 3) * 2;
            *(float2*)(C + (size_t)row * N + col) =
                make_float2(acc[mt][nt][0], acc[mt][nt][1]);
            *(float2*)(C + (size_t)(row + 8) * N + col) =
                make_float2(acc[mt][nt][2], acc[mt][nt][3]);
        }
    }
}

// ---------------------------------------------------------------------------
// RoPE + split (fast-math). q pre-scaled by (1/sqrt(128))*log2(e) so flash
// softmax runs in the exp2 domain.
// ---------------------------------------------------------------------------
__global__ __launch_bounds__(256) void rope_split_kernel(
    const float* __restrict__ qkv, const int* __restrict__ positions,
    __nv_bfloat16* __restrict__ qhi, __nv_bfloat16* __restrict__ qlo,
    __nv_bfloat16* __restrict__ khi, __nv_bfloat16* __restrict__ klo,
    __nv_bfloat16* __restrict__ vhi, __nv_bfloat16* __restrict__ vlo)
{
    int idx  = blockIdx.x * blockDim.x + threadIdx.x;
    int d    = idx & 63;
    int t    = idx >> 6;
    int head = t % 48;
    int tok  = t / 48;
    const float scale = 0.12751744f;   // (1/sqrt(128)) * log2(e)

    if (head < 40) {
        float pos = (float)positions[tok];
        float freq = pos * __expf(-(float)d * 0.21586735246819178f);
        float s, c;
        __sincosf(freq, &s, &c);
        const float* p = qkv + (size_t)tok * QKV_N +
                         (head < 32 ? head * 128 : 4096 + (head - 32) * 128);
        float x1 = p[d], x2 = p[d + 64];
        float r1 = x1 * c - x2 * s;
        float r2 = x2 * c + x1 * s;
        __nv_bfloat16 *dh, *dl;
        if (head < 32) {
            r1 *= scale; r2 *= scale;
            size_t o = ((size_t)tok * NHEADS + head) * HDIM;
            dh = qhi + o; dl = qlo + o;
        } else {
            size_t o = ((size_t)tok * NKV + (head - 32)) * HDIM;
            dh = khi + o; dl = klo + o;
        }
        __nv_bfloat16 h1 = __float2bfloat16(r1);
        __nv_bfloat16 h2 = __float2bfloat16(r2);
        dh[d]      = h1;  dl[d]      = __float2bfloat16(r1 - __bfloat162float(h1));
        dh[d + 64] = h2;  dl[d + 64] = __float2bfloat16(r2 - __bfloat162float(h2));
    } else {
        int gk = head - 40;
        const float* p = qkv + (size_t)tok * QKV_N + 5120 + gk * 128;
        size_t o = ((size_t)tok * NKV + gk) * HDIM;
        float x1 = p[d], x2 = p[d + 64];
        __nv_bfloat16 h1 = __float2bfloat16(x1);
        __nv_bfloat16 h2 = __float2bfloat16(x2);
        vhi[o + d]      = h1;  vlo[o + d]      = __float2bfloat16(x1 - __bfloat162float(h1));
        vhi[o + d + 64] = h2;  vlo[o + d + 64] = __float2bfloat16(x2 - __bfloat162float(h2));
    }
}

// ---------------------------------------------------------------------------
// Flash attention v4: r16 base + (a) Q fragments hoisted to registers,
// (b) per-lane deferred l-sum (no shuffles in the jt loop for the sum),
// (c) exp2-domain softmax (q pre-scaled by log2e).
// 2 CTAs/SM, 64-row q-tiles, 32-row KV cp.async stages, longest-first.
// ---------------------------------------------------------------------------
#define FL3_STAGE      32768
#define FL3_SMEM_BYTES (32768 + 2 * FL3_STAGE)

__device__ __forceinline__ void fl3_kv_load(
    uint32_t st_base,
    const __nv_bfloat16* __restrict__ khi, const __nv_bfloat16* __restrict__ klo,
    const __nv_bfloat16* __restrict__ vhi, const __nv_bfloat16* __restrict__ vlo,
    int b, int g, int jt, int tid)
{
#pragma unroll
    for (int i = 0; i < 16; i++) {
        int lin = tid + 128 * i;          // 0..2047 16B units
        int sel = lin >> 9, rem = lin & 511;
        int r = rem >> 4, u = rem & 15;   // r: 0..31, u: 0..15
        const __nv_bfloat16* base =
            (sel == 0) ? khi : (sel == 1) ? klo : (sel == 2) ? vhi : vlo;
        const __nv_bfloat16* src =
            base + ((size_t)(b * SEQ + jt * 32 + r) * NKV + g) * HDIM + u * 8;
        uint32_t dst = st_base + sel * 8192 + r * 256 + ((u ^ (r & 7)) << 4);
        cp_async16(dst, src);
    }
    CP_COMMIT();
}

__global__ __launch_bounds__(128) void flash_mma4_kernel(
    const __nv_bfloat16* __restrict__ qhi, const __nv_bfloat16* __restrict__ qlo,
    const __nv_bfloat16* __restrict__ khi, const __nv_bfloat16* __restrict__ klo,
    const __nv_bfloat16* __restrict__ vhi, const __nv_bfloat16* __restrict__ vlo,
    __nv_bfloat16* __restrict__ out_hi, __nv_bfloat16* __restrict__ out_lo)
{
    extern __shared__ char sm[];
    const uint32_t smu = smem_u32(sm);
    const uint32_t sQh = smu;
    const uint32_t sQl = smu + 16384;

    const int tid  = threadIdx.x;
    const int wid  = tid >> 5;            // 0..3
    const int lane = tid & 31;

    const int qt = 31 - (blockIdx.x & 31);   // longest-first: 32 q-tiles of 64
    const int h  = (blockIdx.x >> 5) & 31;
    const int b  = blockIdx.x >> 10;
    const int g  = h >> 2;

    const int grp = lane >> 3, tt = lane & 7;
    const int rowA = tt + (grp & 1) * 8, duA = grp >> 1;
    const int rowB = tt + (grp >> 1) * 8, duB = grp & 1;
    const int rowV = tt + (grp & 1) * 8, dnV = grp >> 1;

    // ---- KV stage-0 prefetch first (async; independent of Q smem region)
    fl3_kv_load(smu + 32768, khi, klo, vhi, vlo, b, g, 0, tid);

    // ---- load Q tile to smem staging: 64 rows hi+lo = 2048 x 16B
#pragma unroll
    for (int i = 0; i < 16; i++) {
        int lin = tid + 128 * i;
        int half = lin >> 10, rem = lin & 1023;
        int r = rem >> 4, u = rem & 15;
        const __nv_bfloat16* src = (half ? qlo : qhi) +
            ((size_t)(b * SEQ + qt * 64 + r) * NHEADS + h) * HDIM + u * 8;
        uint32_t doff = (half ? 16384 : 0) + r * 256 + ((u ^ (r & 7)) << 4);
        *(uint4*)(sm + doff) = *(const uint4*)src;
    }
    __syncthreads();

    // ---- hoist Q fragments into registers (loop-invariant per warp)
    uint32_t qH[8][4], qL[8][4];
    {
        int row = wid * 16 + rowA;
#pragma unroll
        for (int ks = 0; ks < 8; ks++) {
            uint32_t off = row * 256 + ((((ks * 2) + duA) ^ (row & 7)) << 4);
            ldsm4(qH[ks], sQh + off);
            ldsm4(qL[ks], sQl + off);
        }
    }

    float m0 = -1e30f, m1 = -1e30f;
    float l0 = 0.0f, l1 = 0.0f;            // per-lane partial sums
    float oacc[16][4];
#pragma unroll
    for (int i = 0; i < 16; i++)
#pragma unroll
        for (int r = 0; r < 4; r++) oacc[i][r] = 0.0f;

    const int njt = 2 * qt + 2;           // 32-row KV tiles

    for (int jt = 0; jt < njt; jt++) {
        asm volatile("cp.async.wait_group 0;" ::: "memory");
        __syncthreads();
        if (jt + 1 < njt)
            fl3_kv_load(smu + 32768 + ((jt + 1) & 1) * FL3_STAGE,
                        khi, klo, vhi, vlo, b, g, jt + 1, tid);

        const uint32_t st  = smu + 32768 + (jt & 1) * FL3_STAGE;
        const uint32_t sKh = st,          sKl = st + 8192;
        const uint32_t sVh = st + 16384,  sVl = st + 24576;

        // ---- S = Q K^T (warp: 16 q-rows x 32 k-cols), Q from registers
        float sacc[4][4];
#pragma unroll
        for (int i = 0; i < 4; i++)
#pragma unroll
            for (int r = 0; r < 4; r++) sacc[i][r] = 0.0f;

#pragma unroll
        for (int ks = 0; ks < 8; ks++) {
            const int u0 = ks * 2;
#pragma unroll
            for (int p = 0; p < 2; p++) {
                int row = p * 16 + rowB;
                uint32_t off = row * 256 + (((u0 + duB) ^ (row & 7)) << 4);
                uint32_t rh[4], rl[4];
                ldsm4(rh, sKh + off);
                ldsm4(rl, sKl + off);
                uint32_t bh0[2] = {rh[0], rh[1]}, bh1[2] = {rh[2], rh[3]};
                uint32_t bl0[2] = {rl[0], rl[1]}, bl1[2] = {rl[2], rl[3]};
                mma_bf16(sacc[2*p],   qH[ks], bh0);
                mma_bf16(sacc[2*p],   qH[ks], bl0);
                mma_bf16(sacc[2*p],   qL[ks], bh0);
                mma_bf16(sacc[2*p+1], qH[ks], bh1);
                mma_bf16(sacc[2*p+1], qH[ks], bl1);
                mma_bf16(sacc[2*p+1], qL[ks], bh1);
            }
        }

        // ---- causal mask (global indices; only tiles crossing the diagonal)
        {
            int rmin = qt * 64 + wid * 16;
            if (jt * 32 + 31 > rmin) {
                int r0 = rmin + (lane >> 2);
#pragma unroll
                for (int nt = 0; nt < 4; nt++) {
                    int col = jt * 32 + nt * 8 + (lane & 3) * 2;
                    if (col     > r0)     sacc[nt][0] = -1e30f;
                    if (col + 1 > r0)     sacc[nt][1] = -1e30f;
                    if (col     > r0 + 8) sacc[nt][2] = -1e30f;
                    if (col + 1 > r0 + 8) sacc[nt][3] = -1e30f;
                }
            }
        }

        // ---- online softmax in exp2 domain (max shuffled; sum per-lane)
        float mx0 = -1e30f, mx1 = -1e30f;
#pragma unroll
        for (int nt = 0; nt < 4; nt++) {
            mx0 = fmaxf(mx0, fmaxf(sacc[nt][0], sacc[nt][1]));
            mx1 = fmaxf(mx1, fmaxf(sacc[nt][2], sacc[nt][3]));
        }
        mx0 = fmaxf(mx0, __shfl_xor_sync(0xffffffffu, mx0, 1));
        mx0 = fmaxf(mx0, __shfl_xor_sync(0xffffffffu, mx0, 2));
        mx1 = fmaxf(mx1, __shfl_xor_sync(0xffffffffu, mx1, 1));
        mx1 = fmaxf(mx1, __shfl_xor_sync(0xffffffffu, mx1, 2));
        float mn0 = fmaxf(m0, mx0), mn1 = fmaxf(m1, mx1);
        float corr0 = exp2f(m0 - mn0), corr1 = exp2f(m1 - mn1);
        m0 = mn0; m1 = mn1;

        float sum0 = 0.0f, sum1 = 0.0f;
#pragma unroll
        for (int nt = 0; nt < 4; nt++) {
            sacc[nt][0] = exp2f(sacc[nt][0] - mn0);
            sacc[nt][1] = exp2f(sacc[nt][1] - mn0);
            sacc[nt][2] = exp2f(sacc[nt][2] - mn1);
            sacc[nt][3] = exp2f(sacc[nt][3] - mn1);
            sum0 += sacc[nt][0] + sacc[nt][1];
            sum1 += sacc[nt][2] + sacc[nt][3];
        }
        l0 = l0 * corr0 + sum0;           // per-lane partial (reduced at end)
        l1 = l1 * corr1 + sum1;

#pragma unroll
        for (int nt = 0; nt < 16; nt++) {
            oacc[nt][0] *= corr0; oacc[nt][1] *= corr0;
            oacc[nt][2] *= corr1; oacc[nt][3] *= corr1;
        }

        // ---- O += P V (P split hi/lo in registers, V via ldmatrix.trans)
#pragma unroll
        for (int kt = 0; kt < 2; kt++) {
            const float* sa = sacc[2*kt];
            const float* sb = sacc[2*kt+1];
            float h00 = __bfloat162float(__float2bfloat16(sa[0]));
            float h01 = __bfloat162float(__float2bfloat16(sa[1]));
            float h02 = __bfloat162float(__float2bfloat16(sa[2]));
            float h03 = __bfloat162float(__float2bfloat16(sa[3]));
            float h10 = __bfloat162float(__float2bfloat16(sb[0]));
            float h11 = __bfloat162float(__float2bfloat16(sb[1]));
            float h12 = __bfloat162float(__float2bfloat16(sb[2]));
            float h13 = __bfloat162float(__float2bfloat16(sb[3]));
            uint32_t ah[4], al[4];
            ah[0] = pack_bf16(h00, h01);  al[0] = pack_bf16(sa[0]-h00, sa[1]-h01);
            ah[1] = pack_bf16(h02, h03);  al[1] = pack_bf16(sa[2]-h02, sa[3]-h03);
            ah[2] = pack_bf16(h10, h11);  al[2] = pack_bf16(sb[0]-h10, sb[1]-h11);
            ah[3] = pack_bf16(h12, h13);  al[3] = pack_bf16(sb[2]-h12, sb[3]-h13);

#pragma unroll
            for (int nn = 0; nn < 8; nn++) {
                int row = kt * 16 + rowV;
                int u = nn * 2 + dnV;
                uint32_t off = row * 256 + ((u ^ (row & 7)) << 4);
                uint32_t rvh[4], rvl[4];
                ldsm4t(rvh, sVh + off);
                ldsm4t(rvl, sVl + off);
                uint32_t bh0[2] = {rvh[0], rvh[1]}, bh1[2] = {rvh[2], rvh[3]};
                uint32_t bl0[2] = {rvl[0], rvl[1]}, bl1[2] = {rvl[2], rvl[3]};
                mma_bf16(oacc[2*nn],   ah, bh0);
                mma_bf16(oacc[2*nn],   ah, bl0);
                mma_bf16(oacc[2*nn],   al, bh0);
                mma_bf16(oacc[2*nn+1], ah, bh1);
                mma_bf16(oacc[2*nn+1], ah, bl1);
                mma_bf16(oacc[2*nn+1], al, bh1);
            }
        }
    }

    // ---- epilogue: reduce l across lane quad, normalize, split, write
    l0 += __shfl_xor_sync(0xffffffffu, l0, 1);
    l0 += __shfl_xor_sync(0xffffffffu, l0, 2);
    l1 += __shfl_xor_sync(0xffffffffu, l1, 1);
    l1 += __shfl_xor_sync(0xffffffffu, l1, 2);
    float inv0 = 1.0f / l0, inv1 = 1.0f / l1;
    size_t row0 = (size_t)(b * SEQ + qt * 64 + wid * 16 + (lane >> 2));
    size_t row1 = row0 + 8;
#pragma unroll
    for (int nt = 0; nt < 16; nt++) {
        int col = h * 128 + nt * 8 + (lane & 3) * 2;
        float v00 = oacc[nt][0] * inv0, v01 = oacc[nt][1] * inv0;
        float v10 = oacc[nt][2] * inv1, v11 = oacc[nt][3] * inv1;
        __nv_bfloat16 a0 = __float2bfloat16(v00), a1 = __float2bfloat16(v01);
        __nv_bfloat16 b0 = __float2bfloat16(v10), b1 = __float2bfloat16(v11);
        *(__nv_bfloat162*)(out_hi + row0 * HID + col) = __nv_bfloat162(a0, a1);
        *(__nv_bfloat162*)(out_lo + row0 * HID + col) = __nv_bfloat162(
            __float2bfloat16(v00 - __bfloat162float(a0)),
            __float2bfloat16(v01 - __bfloat162float(a1)));
        *(__nv_bfloat162*)(out_hi + row1 * HID + col) = __nv_bfloat162(b0, b1);
        *(__nv_bfloat162*)(out_lo + row1 * HID + col) = __nv_bfloat162(
            __float2bfloat16(v10 - __bfloat162float(b0)),
            __float2bfloat16(v11 - __bfloat162float(b1)));
    }
}

// ---------------------------------------------------------------------------
extern "C" void kernel_launch(void* const* d_in, const int* in_sizes, int n_in,
                              void* d_out, int out_size)
{
    const float* hidden    = (const float*)d_in[0];
    const int*   positions = (const int*)  d_in[1];
    const float* w_qkv     = (const float*)d_in[2];
    const float* w_o       = (const float*)d_in[3];
    float*       out       = (float*)d_out;

    float* qkv;
    cudaGetSymbolAddress((void**)&qkv, g_qkv);
    __nv_bfloat16 *hid_hi, *hid_lo, *wqkv_hi, *wqkv_lo;
    __nv_bfloat16 *attn_hi, *attn_lo, *wo_hi, *wo_lo;
    __nv_bfloat16 *q_hi, *q_lo, *k_hi, *k_lo, *v_hi, *v_lo;
    cudaGetSymbolAddress((void**)&hid_hi,  g_hid_hi);
    cudaGetSymbolAddress((void**)&hid_lo,  g_hid_lo);
    cudaGetSymbolAddress((void**)&wqkv_hi, g_wqkv_hi);
    cudaGetSymbolAddress((void**)&wqkv_lo, g_wqkv_lo);
    cudaGetSymbolAddress((void**)&attn_hi, g_attn_hi);
    cudaGetSymbolAddress((void**)&attn_lo, g_attn_lo);
    cudaGetSymbolAddress((void**)&wo_hi,   g_wo_hi);
    cudaGetSymbolAddress((void**)&wo_lo,   g_wo_lo);
    cudaGetSymbolAddress((void**)&q_hi,    g_q_hi);
    cudaGetSymbolAddress((void**)&q_lo,    g_q_lo);
    cudaGetSymbolAddress((void**)&k_hi,    g_k_hi);
    cudaGetSymbolAddress((void**)&k_lo,    g_k_lo);
    cudaGetSymbolAddress((void**)&v_hi,    g_v_hi);
    cudaGetSymbolAddress((void**)&v_lo,    g_v_lo);

    cudaFuncSetAttribute(mma_gemm_ca,
                         cudaFuncAttributeMaxDynamicSharedMemorySize,
                         GEMM_SMEM_BYTES);
    cudaFuncSetAttribute(flash_mma4_kernel,
                         cudaFuncAttributeMaxDynamicSharedMemorySize,
                         FL3_SMEM_BYTES);

    // 0) split all three fp32 inputs to bf16 hi/lo in one launch
    split_all_kernel<<<(unsigned)(N_ALL / 1024), 256>>>(
        hidden, w_qkv, w_o,
        hid_hi, hid_lo, wqkv_hi, wqkv_lo, wo_hi, wo_lo);

    // 1) qkv = hidden @ w_qkv^T  (tensor cores, cp.async pipelined)
    mma_gemm_ca<<<dim3(QKV_N / 64, MTOK / 128), 256, GEMM_SMEM_BYTES>>>(
        hid_hi, hid_lo, wqkv_hi, wqkv_lo, qkv, MTOK, QKV_N, HID);

    // 2) RoPE + split q/k/v to bf16 hi/lo (q pre-scaled incl. log2e)
    rope_split_kernel<<<(BATCH * SEQ * 48 * 64) / 256, 256>>>(
        qkv, positions, q_hi, q_lo, k_hi, k_lo, v_hi, v_lo);

    // 3) causal GQA flash attention v4 (Q-in-regs, deferred sum, exp2)
    flash_mma4_kernel<<<BATCH * NHEADS * (SEQ / 64), 128, FL3_SMEM_BYTES>>>(
        q_hi, q_lo, k_hi, k_lo, v_hi, v_lo, attn_hi, attn_lo);

    // 4) out = attn @ w_o^T (tensor cores, cp.async pipelined)
    mma_gemm_ca<<<dim3(HID / 64, MTOK / 128), 256, GEMM_SMEM_BYTES>>>(
        attn_hi, attn_lo, wo_hi, wo_lo, out, MTOK, HID, HID);
}